// round 1
// baseline (speedup 1.0000x reference)
#include <cuda_runtime.h>

#define NN 256
#define BB 64
#define GAMMA 0.01f
#define INVG 100.0f
#define FBIG 1e8f

// R matrix scratch, diagonal-major per batch: diag d (d=2..2N) stored
// contiguously at start(d) = sum of previous diag lengths, indexed by (i - imin).
// 64 * 256 * 256 * 4B = 16 MB -> stays resident in L2 (126 MB).
__device__ float g_R[BB * NN * NN];
__device__ float g_partV[BB];
__device__ float g_partE[BB];

__global__ __launch_bounds__(256) void dilate_fb_kernel(
    const float* __restrict__ y_pred,
    const float* __restrict__ y_true)
{
    __shared__ float s_o[NN], s_t[NN];
    __shared__ float bufA[NN + 2], bufB[NN + 2], bufC[NN + 2];
    __shared__ float ebufA[NN + 2], ebufB[NN + 2], ebufC[NN + 2];
    __shared__ float s_red[256];

    const int b   = blockIdx.x;
    const int tid = threadIdx.x;
    const int i   = tid + 1;            // DP row owned by this thread (1..N)

    s_o[tid] = y_pred[b * NN + tid];    // o_j
    s_t[tid] = y_true[b * NN + tid];    // t_i

    // ---- init diagonal buffers for forward ----
    for (int k = tid; k < NN + 2; k += 256) {
        bufA[k] = FBIG;   // diag 0: only (0,0)=0, rest boundary
        bufB[k] = FBIG;   // diag 1: V[0][1]=V[1][0]=BIG
    }
    __syncthreads();
    if (tid == 0) bufA[0] = 0.0f;       // V[0][0] = 0
    __syncthreads();

    float* d2  = bufA;   // diag d-2, index by i:  V[i][d-2-i]
    float* d1  = bufB;   // diag d-1
    float* cur = bufC;   // diag d

    const float ti = s_t[tid];          // t_{i-1} (0-indexed), i.e. D row value
    float* Rb = g_R + ((size_t)b * (NN * NN));

    // ================= FORWARD soft-DTW =================
    int dstart = 0;                     // start(d) running offset
    float vNN = 0.0f;
    for (int d = 2; d <= 2 * NN; ++d) {
        int j    = d - i;
        int imin = max(1, d - NN);
        int len  = min(NN, d - 1) - imin + 1;
        if (j >= 1 && j <= NN) {
            float a  = d1[i];           // left V[i][j-1]
            float bq = d1[i - 1];       // up   V[i-1][j]
            float c  = d2[i - 1];       // diag V[i-1][j-1]
            float m  = fminf(a, fminf(bq, c));
            float s  = __expf((m - a)  * INVG)
                     + __expf((m - bq) * INVG)
                     + __expf((m - c)  * INVG);
            float diff = ti - s_o[j - 1];
            float v = fmaf(diff, diff, m) - GAMMA * __logf(s);
            cur[i] = v;
            Rb[dstart + (i - imin)] = v;   // coalesced diagonal-major store
            if (d == 2 * NN) vNN = v;      // only i==N thread hits this
        }
        if (tid == 0) {
            cur[0] = FBIG;                 // V[0][d] boundary
            if (d <= NN) cur[d] = FBIG;    // V[d][0] boundary
        }
        dstart += len;
        __syncthreads();
        float* tmp = d2; d2 = d1; d1 = cur; cur = tmp;
    }
    if (tid == NN - 1) g_partV[b] = vNN;   // V[N][N]

    // ================= BACKWARD gradient E =================
    for (int k = tid; k < NN + 2; k += 256) {
        ebufA[k] = 0.0f; ebufB[k] = 0.0f; ebufC[k] = 0.0f;
        bufA[k]  = 0.0f; bufB[k]  = 0.0f; bufC[k]  = 0.0f;
    }
    __syncthreads();

    float* e1   = ebufA;   // E on diag d+1
    float* e2   = ebufB;   // E on diag d+2
    float* ecur = ebufC;
    float* r1   = bufA;    // R on diag d+1
    float* r2   = bufB;    // R on diag d+2
    float* rcur = bufC;

    float sumE = 0.0f;
    int dend = NN * NN;                 // becomes start(d) after subtraction
    for (int d = 2 * NN; d >= 2; --d) {
        int j    = d - i;
        int imin = max(1, d - NN);
        int len  = min(NN, d - 1) - imin + 1;
        dend -= len;                    // = start(d)

        float e = 0.0f, Rij = 0.0f;
        if (j >= 1 && j <= NN) {
            Rij = Rb[dend + (i - imin)];   // coalesced load, L2-resident
            if (i == NN && j == NN) {
                e = 1.0f;                  // E[N][N] (virtual corner term)
            } else {
                float oj = s_o[j - 1];
                if (i < NN) {              // down neighbor (i+1, j)
                    float tip = s_t[i];
                    float dd  = tip - oj;
                    e = __expf((r1[i + 1] - Rij - dd * dd) * INVG) * e1[i + 1];
                }
                if (j < NN) {              // right neighbor (i, j+1)
                    float ojp = s_o[j];
                    float dd  = ti - ojp;
                    e += __expf((r1[i] - Rij - dd * dd) * INVG) * e1[i];
                }
                if (i < NN && j < NN) {    // diag neighbor (i+1, j+1)
                    float tip = s_t[i];
                    float ojp = s_o[j];
                    float dd  = tip - ojp;
                    e += __expf((r2[i + 1] - Rij - dd * dd) * INVG) * e2[i + 1];
                }
            }
            float w = (float)(i - j);      // omega = (i-j)^2 (1-indexed == diff)
            sumE = fmaf(e, w * w, sumE);
        }
        ecur[i] = e;                       // unconditional: invalid cells -> 0
        rcur[i] = Rij;
        __syncthreads();
        float* tmp;
        tmp = e2; e2 = e1; e1 = ecur; ecur = tmp;
        tmp = r2; r2 = r1; r1 = rcur; rcur = tmp;
    }

    // ---- block reduction of sum(E * omega), fixed order ----
    s_red[tid] = sumE;
    __syncthreads();
    #pragma unroll
    for (int off = 128; off > 0; off >>= 1) {
        if (tid < off) s_red[tid] += s_red[tid + off];
        __syncthreads();
    }
    if (tid == 0) g_partE[b] = s_red[0];
}

__global__ void finalize_kernel(float* __restrict__ out) {
    // single thread, deterministic summation order
    float sv = 0.0f, se = 0.0f;
    for (int b = 0; b < BB; ++b) {
        sv += g_partV[b];
        se += g_partE[b];
    }
    float loss_shape    = sv / (float)BB;
    float loss_temporal = se / ((float)BB * (float)(NN * NN));
    out[0] = 0.5f * loss_shape + 0.5f * loss_temporal;
}

extern "C" void kernel_launch(void* const* d_in, const int* in_sizes, int n_in,
                              void* d_out, int out_size) {
    const float* y_pred = (const float*)d_in[0];
    const float* y_true = (const float*)d_in[1];
    dilate_fb_kernel<<<BB, 256>>>(y_pred, y_true);
    finalize_kernel<<<1, 1>>>((float*)d_out);
}

// round 2
// speedup vs baseline: 1.2108x; 1.2108x over previous
#include <cuda_runtime.h>

#define NN 256
#define BB 64
#define GAMMA 0.01f
#define INVG 100.0f
#define FBIG 1e8f

// R matrix scratch, diagonal-major per batch: diag d (d=2..2N) stored
// contiguously at diag_start(d), indexed by (i - imin). 16 MB -> L2-resident.
__device__ float g_R[BB * NN * NN];
__device__ float g_partV[BB];
__device__ float g_partE[BB];

__device__ __forceinline__ int diag_start(int d) {
    // start offset of diag d (d in [2, 2N]) in diagonal-major storage
    return (d <= NN + 1)
        ? (((d - 1) * (d - 2)) >> 1)
        : (NN * NN - (((2 * NN + 1 - d) * (2 * NN + 2 - d)) >> 1));
}

__device__ __forceinline__ float ld_diag(const float* __restrict__ Rb, int d, int i) {
    int j = d - i;
    if (j < 1 || j > NN) return 0.0f;
    int imin = max(1, d - NN);
    return __ldg(Rb + diag_start(d) + (i - imin));
}

__global__ void dummy_kernel() {}

__global__ __launch_bounds__(256) void dilate_fb_kernel(
    const float* __restrict__ y_pred,
    const float* __restrict__ y_true)
{
    __shared__ float s_o[NN], s_t[NN];
    __shared__ float bufA[NN + 2], bufB[NN + 2], bufC[NN + 2];
    __shared__ float ebufA[NN + 2], ebufB[NN + 2], ebufC[NN + 2];
    __shared__ float s_red[256];

    const int b   = blockIdx.x;
    const int tid = threadIdx.x;
    const int i   = tid + 1;            // DP row owned by this thread (1..N)

    s_o[tid] = y_pred[b * NN + tid];    // o_j
    s_t[tid] = y_true[b * NN + tid];    // t_i

    // init all three forward diag buffers to FBIG (boundaries)
    for (int k = tid; k < NN + 2; k += 256) {
        bufA[k] = FBIG; bufB[k] = FBIG; bufC[k] = FBIG;
    }
    __syncthreads();

    float* d2  = bufA;   // diag d-2, index by i: V[i][(d-2)-i]
    float* d1  = bufB;   // diag d-1
    float* cur = bufC;   // diag d

    const float ti = s_t[tid];          // t_{i-1}
    float* Rb = g_R + ((size_t)b * (NN * NN));

    // ================= FORWARD soft-DTW =================
    int dstart = 0;
    float vprev = FBIG;                 // own V[i][j-1] (left), carried in reg
    float vNN = 0.0f;
    for (int d = 2; d <= 2 * NN; ++d) {
        int j    = d - i;
        int imin = max(1, d - NN);
        int len  = min(NN, d - 1) - imin + 1;
        if (j >= 1 && j <= NN) {
            float bq = d1[i - 1];                      // up   V[i-1][j]
            float c  = (d == 2) ? 0.0f : d2[i - 1];    // diag V[i-1][j-1]; V[0][0]=0
            float a  = vprev;                          // left V[i][j-1]
            float m  = fminf(a, fminf(bq, c));
            float s  = __expf((m - a)  * INVG)
                     + __expf((m - bq) * INVG)
                     + __expf((m - c)  * INVG);
            float diff = ti - s_o[j - 1];
            float v = fmaf(diff, diff, m) - GAMMA * __logf(s);
            cur[i] = v;
            vprev  = v;
            Rb[dstart + (i - imin)] = v;   // coalesced diagonal-major store
            if (d == 2 * NN) vNN = v;
        } else if (j == 0) {
            cur[i] = FBIG;                 // column-0 boundary V[i][0]
            vprev  = FBIG;
        }
        dstart += len;
        __syncthreads();
        float* tmp = d2; d2 = d1; d1 = cur; cur = tmp;
    }
    if (tid == NN - 1) g_partV[b] = vNN;   // V[N][N]

    // ================= BACKWARD gradient E =================
    for (int k = tid; k < NN + 2; k += 256) {
        ebufA[k] = 0.0f; ebufB[k] = 0.0f; ebufC[k] = 0.0f;
        bufA[k]  = 0.0f; bufB[k]  = 0.0f; bufC[k]  = 0.0f;
    }
    __syncthreads();

    float* e1   = ebufA;   // E on diag d+1
    float* e2   = ebufB;   // E on diag d+2
    float* ecur = ebufC;
    float* r1   = bufA;    // R on diag d+1
    float* r2   = bufB;    // R on diag d+2
    float* rcur = bufC;

    float eprev = 0.0f;    // own E[i][j+1] (right), carried in reg
    float rprev = 0.0f;    // own R[i][j+1]
    float sumE  = 0.0f;

    // software-pipelined R prefetch, depth 3 (hides ~250cyc L2 latency)
    float pf0 = ld_diag(Rb, 2 * NN,     i);
    float pf1 = ld_diag(Rb, 2 * NN - 1, i);
    float pf2 = ld_diag(Rb, 2 * NN - 2, i);

    for (int d = 2 * NN; d >= 2; --d) {
        int j = d - i;
        float Rij = pf0;
        pf0 = pf1;
        pf1 = pf2;
        pf2 = (d - 3 >= 2) ? ld_diag(Rb, d - 3, i) : 0.0f;

        float e = 0.0f;
        if (j >= 1 && j <= NN) {
            if (i == NN && j == NN) {
                e = 1.0f;                      // E[N][N]
            } else {
                if (i < NN) {                  // down neighbor (i+1, j)
                    float dd = s_t[i] - s_o[j - 1];
                    e = __expf((r1[i + 1] - Rij - dd * dd) * INVG) * e1[i + 1];
                }
                if (j < NN) {                  // right neighbor (i, j+1) — own regs
                    float dd = ti - s_o[j];
                    e = fmaf(__expf((rprev - Rij - dd * dd) * INVG), eprev, e);
                }
                if (i < NN && j < NN) {        // diag neighbor (i+1, j+1)
                    float dd = s_t[i] - s_o[j];
                    e = fmaf(__expf((r2[i + 1] - Rij - dd * dd) * INVG), e2[i + 1], e);
                }
            }
            float w = (float)(i - j);          // omega = (i-j)^2
            sumE = fmaf(e, w * w, sumE);
        }
        ecur[i] = e;       // invalid cells write 0
        rcur[i] = Rij;     // ld_diag returned 0 for invalid cells
        eprev = e;
        rprev = Rij;
        __syncthreads();
        float* tmp;
        tmp = e2; e2 = e1; e1 = ecur; ecur = tmp;
        tmp = r2; r2 = r1; r1 = rcur; rcur = tmp;
    }

    // ---- block reduction of sum(E * omega), fixed order ----
    s_red[tid] = sumE;
    __syncthreads();
    #pragma unroll
    for (int off = 128; off > 0; off >>= 1) {
        if (tid < off) s_red[tid] += s_red[tid + off];
        __syncthreads();
    }
    if (tid == 0) g_partE[b] = s_red[0];
}

__global__ void finalize_kernel(float* __restrict__ out) {
    // one warp; deterministic shfl-tree reduction
    int t = threadIdx.x;
    float sv = g_partV[t] + g_partV[t + 32];
    float se = g_partE[t] + g_partE[t + 32];
    #pragma unroll
    for (int off = 16; off > 0; off >>= 1) {
        sv += __shfl_down_sync(0xffffffffu, sv, off);
        se += __shfl_down_sync(0xffffffffu, se, off);
    }
    if (t == 0) {
        float loss_shape    = sv * (1.0f / (float)BB);
        float loss_temporal = se * (1.0f / ((float)BB * (float)(NN * NN)));
        out[0] = 0.5f * loss_shape + 0.5f * loss_temporal;
    }
}

extern "C" void kernel_launch(void* const* d_in, const int* in_sizes, int n_in,
                              void* d_out, int out_size) {
    const float* y_pred = (const float*)d_in[0];
    const float* y_true = (const float*)d_in[1];
    // launch pattern [dummy, fb, fin, dummy]: ncu (-s 5 -c 1) lands on fb
    dummy_kernel<<<1, 1>>>();
    dilate_fb_kernel<<<BB, 256>>>(y_pred, y_true);
    finalize_kernel<<<1, 32>>>((float*)d_out);
    dummy_kernel<<<1, 1>>>();
}